// round 11
// baseline (speedup 1.0000x reference)
#include <cuda_runtime.h>
#include <math.h>

#define T_LEN 1024
#define NN    1022            /* templates */
#define PAD   1104            /* max smem read index ~1058 */
#define RR    0.2f
#define NTHR  768
#define NWARP (NTHR / 32)
#define NSLOT 6

typedef unsigned long long u64;

__device__ float g_ent[128];
__device__ unsigned int g_barrier;

__device__ __forceinline__ u64 fma2(u64 a, u64 b, u64 c) {
    u64 r;
    asm("fma.rn.f32x2 %0, %1, %2, %3;" : "=l"(r) : "l"(a), "l"(b), "l"(c));
    return r;
}
__device__ __forceinline__ unsigned int lo32(u64 v) { return (unsigned int)v; }
__device__ __forceinline__ unsigned int hi32(u64 v) { return (unsigned int)(v >> 32); }
// (hi of x, lo of y) -> packed f32x2 {lo=hi32(x), hi=lo32(y)}
__device__ __forceinline__ u64 mkodd(u64 x, u64 y) {
    return (u64)hi32(x) | ((u64)lo32(y) << 32);
}

// ---- single self-contained unit (tail): chunk k0..k0+31 of diagonals
// dbase..dbase+3; 34 booleans/diagonal, MSB-first, sign((a-b)^2 - Rs2). ----
__device__ __forceinline__ void unit_count(const float* __restrict__ xs, int k0, int dbase,
                                           int remBase, float Rs2, u64 NEG1, u64 NRS2,
                                           unsigned int& cm, unsigned int& cm1) {
    const u64* __restrict__ a2p = reinterpret_cast<const u64*>(xs + k0);
    const u64* __restrict__ ep  = reinterpret_cast<const u64*>(xs + k0 + dbase - 1);
    unsigned int acc[4] = {0, 0, 0, 0};
    u64 e0 = ep[0];
    u64 e1 = ep[1];
    u64 oL = mkodd(e0, e1);
    #pragma unroll
    for (int q = 0; q < 8; q++) {
        u64 A0 = a2p[2 * q];
        u64 A1 = a2p[2 * q + 1];
        u64 e2 = ep[2 * q + 2];
        u64 e3 = ep[2 * q + 3];
        u64 o1 = mkodd(e1, e2);
        u64 o2 = mkodd(e2, e3);
        u64 W0[4] = {oL, e1, o1, e2};
        u64 W1[4] = {o1, e2, o2, e3};
        #pragma unroll
        for (int s = 0; s < 4; s++) {
            u64 d = fma2(W0[s], NEG1, A0); u64 u = fma2(d, d, NRS2);
            acc[s] = __funnelshift_l(lo32(u), acc[s], 1);
            acc[s] = __funnelshift_l(hi32(u), acc[s], 1);
            d = fma2(W1[s], NEG1, A1); u = fma2(d, d, NRS2);
            acc[s] = __funnelshift_l(lo32(u), acc[s], 1);
            acc[s] = __funnelshift_l(hi32(u), acc[s], 1);
        }
        e1 = e3; oL = o2;
    }
    const float a32 = xs[k0 + 32];
    const float a33 = xs[k0 + 33];
    #pragma unroll
    for (int s = 0; s < 4; s++) {
        float W33 = xs[k0 + dbase + 32 + s];
        float W34 = xs[k0 + dbase + 33 + s];
        float d32 = a32 - W33;
        float d33 = a33 - W34;
        float u32 = fmaf(d32, d32, -Rs2);
        float u33 = fmaf(d33, d33, -Rs2);
        unsigned int ext = (__float_as_uint(u32) & 0x80000000u)
                         | ((__float_as_uint(u33) >> 1) & 0x40000000u);
        int rem = remBase - s;
        unsigned int mask = (rem >= 32) ? 0xffffffffu
                          : ((rem <= 0) ? 0u : (0xffffffffu << (32 - rem)));
        unsigned int S1 = __funnelshift_l(ext, acc[s], 1);
        unsigned int S2 = __funnelshift_l(ext, acc[s], 2);
        unsigned int mm = acc[s] & S1 & mask;
        cm  += __popc(mm);
        cm1 += __popc(mm & S2);
    }
}

// ---- two interleaved independent units: 2 fma2 streams, 8 acc chains,
// 2 LDS streams -> covers fixed-op + LDS latency per warp. ----
__device__ __forceinline__ void unit2_count(const float* __restrict__ xs,
                                            int k0a, int dba, int remA,
                                            int k0b, int dbb, int remB,
                                            float Rs2, u64 NEG1, u64 NRS2,
                                            unsigned int& cm, unsigned int& cm1) {
    const u64* __restrict__ a2pA = reinterpret_cast<const u64*>(xs + k0a);
    const u64* __restrict__ epA  = reinterpret_cast<const u64*>(xs + k0a + dba - 1);
    const u64* __restrict__ a2pB = reinterpret_cast<const u64*>(xs + k0b);
    const u64* __restrict__ epB  = reinterpret_cast<const u64*>(xs + k0b + dbb - 1);
    unsigned int accA[4] = {0, 0, 0, 0};
    unsigned int accB[4] = {0, 0, 0, 0};
    u64 e1A, oLA, e1B, oLB;
    { u64 e0 = epA[0]; e1A = epA[1]; oLA = mkodd(e0, e1A); }
    { u64 e0 = epB[0]; e1B = epB[1]; oLB = mkodd(e0, e1B); }
    #pragma unroll
    for (int q = 0; q < 8; q++) {
        u64 A0a = a2pA[2 * q];
        u64 A1a = a2pA[2 * q + 1];
        u64 e2a = epA[2 * q + 2];
        u64 e3a = epA[2 * q + 3];
        u64 A0b = a2pB[2 * q];
        u64 A1b = a2pB[2 * q + 1];
        u64 e2b = epB[2 * q + 2];
        u64 e3b = epB[2 * q + 3];
        u64 o1a = mkodd(e1A, e2a);
        u64 o2a = mkodd(e2a, e3a);
        u64 o1b = mkodd(e1B, e2b);
        u64 o2b = mkodd(e2b, e3b);
        u64 W0a[4] = {oLA, e1A, o1a, e2a};
        u64 W1a[4] = {o1a, e2a, o2a, e3a};
        u64 W0b[4] = {oLB, e1B, o1b, e2b};
        u64 W1b[4] = {o1b, e2b, o2b, e3b};
        #pragma unroll
        for (int s = 0; s < 4; s++) {
            u64 da = fma2(W0a[s], NEG1, A0a); u64 ua = fma2(da, da, NRS2);
            u64 db = fma2(W0b[s], NEG1, A0b); u64 ub = fma2(db, db, NRS2);
            accA[s] = __funnelshift_l(lo32(ua), accA[s], 1);
            accA[s] = __funnelshift_l(hi32(ua), accA[s], 1);
            accB[s] = __funnelshift_l(lo32(ub), accB[s], 1);
            accB[s] = __funnelshift_l(hi32(ub), accB[s], 1);
            da = fma2(W1a[s], NEG1, A1a); ua = fma2(da, da, NRS2);
            db = fma2(W1b[s], NEG1, A1b); ub = fma2(db, db, NRS2);
            accA[s] = __funnelshift_l(lo32(ua), accA[s], 1);
            accA[s] = __funnelshift_l(hi32(ua), accA[s], 1);
            accB[s] = __funnelshift_l(lo32(ub), accB[s], 1);
            accB[s] = __funnelshift_l(hi32(ub), accB[s], 1);
        }
        e1A = e3a; oLA = o2a;
        e1B = e3b; oLB = o2b;
    }
    {
        const float a32 = xs[k0a + 32];
        const float a33 = xs[k0a + 33];
        #pragma unroll
        for (int s = 0; s < 4; s++) {
            float W33 = xs[k0a + dba + 32 + s];
            float W34 = xs[k0a + dba + 33 + s];
            float d32 = a32 - W33;
            float d33 = a33 - W34;
            float u32 = fmaf(d32, d32, -Rs2);
            float u33 = fmaf(d33, d33, -Rs2);
            unsigned int ext = (__float_as_uint(u32) & 0x80000000u)
                             | ((__float_as_uint(u33) >> 1) & 0x40000000u);
            int rem = remA - s;
            unsigned int mask = (rem >= 32) ? 0xffffffffu
                              : ((rem <= 0) ? 0u : (0xffffffffu << (32 - rem)));
            unsigned int S1 = __funnelshift_l(ext, accA[s], 1);
            unsigned int S2 = __funnelshift_l(ext, accA[s], 2);
            unsigned int mm = accA[s] & S1 & mask;
            cm  += __popc(mm);
            cm1 += __popc(mm & S2);
        }
    }
    {
        const float a32 = xs[k0b + 32];
        const float a33 = xs[k0b + 33];
        #pragma unroll
        for (int s = 0; s < 4; s++) {
            float W33 = xs[k0b + dbb + 32 + s];
            float W34 = xs[k0b + dbb + 33 + s];
            float d32 = a32 - W33;
            float d33 = a33 - W34;
            float u32 = fmaf(d32, d32, -Rs2);
            float u33 = fmaf(d33, d33, -Rs2);
            unsigned int ext = (__float_as_uint(u32) & 0x80000000u)
                             | ((__float_as_uint(u33) >> 1) & 0x40000000u);
            int rem = remB - s;
            unsigned int mask = (rem >= 32) ? 0xffffffffu
                              : ((rem <= 0) ? 0u : (0xffffffffu << (32 - rem)));
            unsigned int S1 = __funnelshift_l(ext, accB[s], 1);
            unsigned int S2 = __funnelshift_l(ext, accB[s], 2);
            unsigned int mm = accB[s] & S1 & mask;
            cm  += __popc(mm);
            cm1 += __popc(mm & S2);
        }
    }
}

__global__ __launch_bounds__(NTHR, 1)
void sampen_kernel(const float* __restrict__ pred, const float* __restrict__ tgt,
                   float* __restrict__ out) {
    __shared__ __align__(16) float xs[PAD];
    __shared__ double redA[NWARP], redB[NWARP];
    __shared__ unsigned int redc[NWARP], redc1[NWARP];
    __shared__ float s_thresh2;

    const int s   = blockIdx.x;
    const int tid = threadIdx.x;
    const float* src = (s < 64) ? (pred + (size_t)s * T_LEN)
                                : (tgt  + (size_t)(s - 64) * T_LEN);

    // ---- load raw signal + zero pad ----
    float v0 = src[tid];
    float v1 = (tid + NTHR < T_LEN) ? src[tid + NTHR] : 0.0f;
    xs[tid] = v0;
    if (tid + NTHR < T_LEN) xs[tid + NTHR] = v1;
    for (int i = T_LEN + tid; i < PAD; i += NTHR) xs[i] = 0.0f;

    // ---- std (ddof=1) in double; mean cancels inside |xi-xj|:
    //      squared scaled threshold Rs2 = (R*(std+eps))^2 ----
    double ls  = (double)v0 + (double)v1;
    double ls2 = (double)v0 * (double)v0 + (double)v1 * (double)v1;
    #pragma unroll
    for (int o = 16; o > 0; o >>= 1) {
        ls  += __shfl_down_sync(0xffffffffu, ls,  o);
        ls2 += __shfl_down_sync(0xffffffffu, ls2, o);
    }
    if ((tid & 31) == 0) { redA[tid >> 5] = ls; redB[tid >> 5] = ls2; }
    __syncthreads();
    if (tid == 0) {
        double S = 0.0, S2 = 0.0;
        #pragma unroll
        for (int w = 0; w < NWARP; w++) { S += redA[w]; S2 += redB[w]; }
        double var = (S2 - S * S / (double)T_LEN) / (double)(T_LEN - 1);
        double sd  = sqrt(var);
        double rs  = (double)RR * (sd + 1e-8);
        s_thresh2  = (float)(rs * rs);
    }
    __syncthreads();
    const float Rs2 = s_thresh2;
    const u64 NEG1 = 0xBF800000BF800000ull;               // (-1.0f, -1.0f)
    const unsigned int nr = __float_as_uint(-Rs2);
    const u64 NRS2 = (u64)nr | ((u64)nr << 32);           // (-Rs2, -Rs2)

    // ---- upper-triangle counting: 4-diagonal groups, 2-unit ILP, 6 slots ----
    // Pair (P, 255-P): exactly 33 units. Thread (P = tid&127, sg = tid>>7 in [0,6))
    // owns units [g0, g1): counts {6,5,6,5,6,5}. Two units at a time (ILP);
    // single-unit tail only for 5-unit slots (warp-uniform).
    const int P  = tid & 127;
    const int sg = tid >> 7;           // warp-uniform, 0..5
    const int dA = 4 * P + 1;
    const int LA = NN - dA;            // 1021 - 4P
    const int dB = 1021 - 4 * P;       // partner group 255-P
    const int LB = NN - dB;            // 4P + 1
    const int CA = (LA + 31) >> 5;
    const int g0 = (sg * 33) / NSLOT;
    const int g1 = ((sg + 1) * 33) / NSLOT;

    unsigned int cm = 0, cm1 = 0;
    int j = g0;
    for (; j + 1 < g1; j += 2) {
        bool inA0  = (j < CA);
        int dbase0 = inA0 ? dA : dB;
        int c0     = inA0 ? j  : j - CA;
        int Lb0    = inA0 ? LA : LB;
        int jb     = j + 1;
        bool inA1  = (jb < CA);
        int dbase1 = inA1 ? dA : dB;
        int c1     = inA1 ? jb : jb - CA;
        int Lb1    = inA1 ? LA : LB;
        unit2_count(xs, c0 << 5, dbase0, Lb0 - (c0 << 5),
                        c1 << 5, dbase1, Lb1 - (c1 << 5),
                    Rs2, NEG1, NRS2, cm, cm1);
    }
    if (j < g1) {                       // warp-uniform (5-unit slots)
        bool inA  = (j < CA);
        int dbase = inA ? dA : dB;
        int c     = inA ? j  : j - CA;
        int Lb    = inA ? LA : LB;
        unit_count(xs, c << 5, dbase, Lb - (c << 5), Rs2, NEG1, NRS2, cm, cm1);
    }

    // ---- reduce counts ----
    #pragma unroll
    for (int o = 16; o > 0; o >>= 1) {
        cm  += __shfl_down_sync(0xffffffffu, cm,  o);
        cm1 += __shfl_down_sync(0xffffffffu, cm1, o);
    }
    if ((tid & 31) == 0) { redc[tid >> 5] = cm; redc1[tid >> 5] = cm1; }
    __syncthreads();

    if (tid == 0) {
        unsigned int tm = 0, tm1 = 0;
        #pragma unroll
        for (int w = 0; w < NWARP; w++) { tm += redc[w]; tm1 += redc1[w]; }
        // symmetric matrix + zero diagonal: matches = NN + 2*upper
        unsigned int matches_m  = (unsigned int)NN + 2u * tm;
        unsigned int matches_m1 = (unsigned int)NN + 2u * tm1;
        float ratio = (float)matches_m1 / (float)matches_m;   // matches_m >= NN > 0
        ratio = fmaxf(ratio, 1e-30f);
        g_ent[s] = -logf(ratio);

        // ---- fused finalize: last block computes the MSE ----
        __threadfence();
        unsigned int old = atomicAdd(&g_barrier, 1);
        if (old == 127u) {
            g_barrier = 0;            // reset for next graph replay
            __threadfence();          // make all g_ent writes visible
            float acc = 0.0f;
            #pragma unroll
            for (int i = 0; i < 64; i++) {
                float dp = __ldcg(&g_ent[i]);
                float dt = __ldcg(&g_ent[64 + i]);
                float dd = dp - dt;
                acc += dd * dd;
            }
            out[0] = acc * (1.0f / 64.0f);
        }
    }
}

extern "C" void kernel_launch(void* const* d_in, const int* in_sizes, int n_in,
                              void* d_out, int out_size) {
    const float* pred = (const float*)d_in[0];
    const float* tgt  = (const float*)d_in[1];
    float* out = (float*)d_out;
    sampen_kernel<<<128, NTHR>>>(pred, tgt, out);
}

// round 12
// speedup vs baseline: 1.1116x; 1.1116x over previous
#include <cuda_runtime.h>
#include <math.h>

#define T_LEN 1024
#define NN    1022            /* templates */
#define PAD   1104
#define RR    0.2f
#define NTHR  512
#define NWARP (NTHR / 32)

typedef unsigned long long u64;

__device__ float g_ent[128];
__device__ unsigned int g_barrier;

__device__ __forceinline__ u64 fma2(u64 a, u64 b, u64 c) {
    u64 r;
    asm("fma.rn.f32x2 %0, %1, %2, %3;" : "=l"(r) : "l"(a), "l"(b), "l"(c));
    return r;
}
__device__ __forceinline__ unsigned int lo32(u64 v) { return (unsigned int)v; }
__device__ __forceinline__ unsigned int hi32(u64 v) { return (unsigned int)(v >> 32); }

// Two pairs (lower k first) through FADD-free core:
//   d2 = fma2(W, -1, A); u2 = fma2(d2, d2, -Rs2); insert both sign bits MSB-first.
#define FMA2SH(acc, W, A)                                            \
    do {                                                             \
        u64 _d = fma2((W), NEG1, (A));                               \
        u64 _u = fma2(_d, _d, NRS2);                                 \
        (acc) = __funnelshift_l(lo32(_u), (acc), 1);                 \
        (acc) = __funnelshift_l(hi32(_u), (acc), 1);                 \
    } while (0)

// ---- single self-contained unit (tail): chunk k0..k0+31 of diagonals
// dbase..dbase+3 (dbase ≡ 1 mod 4). All window operands are aligned
// ulonglong2 loads: evens from xs, odds from ys (ys[i] = xs[i+1]). ----
__device__ __forceinline__ void unit_count(const float* __restrict__ xs,
                                           const float* __restrict__ ys,
                                           int k0, int dbase, int remBase,
                                           float Rs2, u64 NEG1, u64 NRS2,
                                           unsigned int& cm, unsigned int& cm1) {
    const int B = k0 + dbase - 1;                     // ≡ 0 mod 4
    const ulonglong2* __restrict__ Ap = reinterpret_cast<const ulonglong2*>(xs + k0);
    const ulonglong2* __restrict__ Ep = reinterpret_cast<const ulonglong2*>(xs + B);
    const ulonglong2* __restrict__ Yp = reinterpret_cast<const ulonglong2*>(ys + B);
    unsigned int acc0 = 0, acc1 = 0, acc2 = 0, acc3 = 0;
    u64 e1 = Ep[0].y;                                 // (B+2, B+3)
    ulonglong2 Y0 = Yp[0];                            // .x = (B+1,B+2), .y = (B+3,B+4)
    #pragma unroll
    for (int q = 0; q < 8; q++) {
        ulonglong2 A  = Ap[q];                        // A.x = pairs 4q..4q+1, A.y = 4q+2..4q+3
        ulonglong2 E1 = Ep[q + 1];                    // .x = e2, .y = e3
        ulonglong2 Y1 = Yp[q + 1];                    // .x = o2
        FMA2SH(acc0, Y0.x, A.x);  FMA2SH(acc0, Y0.y, A.y);   // s=0
        FMA2SH(acc1, e1,   A.x);  FMA2SH(acc1, E1.x, A.y);   // s=1
        FMA2SH(acc2, Y0.y, A.x);  FMA2SH(acc2, Y1.x, A.y);   // s=2
        FMA2SH(acc3, E1.x, A.x);  FMA2SH(acc3, E1.y, A.y);   // s=3
        e1 = E1.y; Y0 = Y1;
    }
    const float a32 = xs[k0 + 32];
    const float a33 = xs[k0 + 33];
    unsigned int acc[4] = {acc0, acc1, acc2, acc3};
    #pragma unroll
    for (int s = 0; s < 4; s++) {
        float W33 = xs[B + 33 + s];
        float W34 = xs[B + 34 + s];
        float d32 = a32 - W33;
        float d33 = a33 - W34;
        float u32 = fmaf(d32, d32, -Rs2);
        float u33 = fmaf(d33, d33, -Rs2);
        unsigned int ext = (__float_as_uint(u32) & 0x80000000u)
                         | ((__float_as_uint(u33) >> 1) & 0x40000000u);
        int rem = remBase - s;
        unsigned int mask = (rem >= 32) ? 0xffffffffu
                          : ((rem <= 0) ? 0u : (0xffffffffu << (32 - rem)));
        unsigned int S1 = __funnelshift_l(ext, acc[s], 1);
        unsigned int S2 = __funnelshift_l(ext, acc[s], 2);
        unsigned int mm = acc[s] & S1 & mask;
        cm  += __popc(mm);
        cm1 += __popc(mm & S2);
    }
}

// ---- two interleaved independent units (ILP x2) ----
__device__ __forceinline__ void unit2_count(const float* __restrict__ xs,
                                            const float* __restrict__ ys,
                                            int k0a, int dba, int remA,
                                            int k0b, int dbb, int remB,
                                            float Rs2, u64 NEG1, u64 NRS2,
                                            unsigned int& cm, unsigned int& cm1) {
    const int BA = k0a + dba - 1;
    const int BB = k0b + dbb - 1;
    const ulonglong2* __restrict__ ApA = reinterpret_cast<const ulonglong2*>(xs + k0a);
    const ulonglong2* __restrict__ EpA = reinterpret_cast<const ulonglong2*>(xs + BA);
    const ulonglong2* __restrict__ YpA = reinterpret_cast<const ulonglong2*>(ys + BA);
    const ulonglong2* __restrict__ ApB = reinterpret_cast<const ulonglong2*>(xs + k0b);
    const ulonglong2* __restrict__ EpB = reinterpret_cast<const ulonglong2*>(xs + BB);
    const ulonglong2* __restrict__ YpB = reinterpret_cast<const ulonglong2*>(ys + BB);
    unsigned int aA0 = 0, aA1 = 0, aA2 = 0, aA3 = 0;
    unsigned int aB0 = 0, aB1 = 0, aB2 = 0, aB3 = 0;
    u64 e1A = EpA[0].y;
    u64 e1B = EpB[0].y;
    ulonglong2 Y0A = YpA[0];
    ulonglong2 Y0B = YpB[0];
    #pragma unroll
    for (int q = 0; q < 8; q++) {
        ulonglong2 Aa  = ApA[q];
        ulonglong2 E1a = EpA[q + 1];
        ulonglong2 Y1a = YpA[q + 1];
        ulonglong2 Ab  = ApB[q];
        ulonglong2 E1b = EpB[q + 1];
        ulonglong2 Y1b = YpB[q + 1];
        FMA2SH(aA0, Y0A.x, Aa.x);  FMA2SH(aB0, Y0B.x, Ab.x);
        FMA2SH(aA0, Y0A.y, Aa.y);  FMA2SH(aB0, Y0B.y, Ab.y);
        FMA2SH(aA1, e1A,   Aa.x);  FMA2SH(aB1, e1B,   Ab.x);
        FMA2SH(aA1, E1a.x, Aa.y);  FMA2SH(aB1, E1b.x, Ab.y);
        FMA2SH(aA2, Y0A.y, Aa.x);  FMA2SH(aB2, Y0B.y, Ab.x);
        FMA2SH(aA2, Y1a.x, Aa.y);  FMA2SH(aB2, Y1b.x, Ab.y);
        FMA2SH(aA3, E1a.x, Aa.x);  FMA2SH(aB3, E1b.x, Ab.x);
        FMA2SH(aA3, E1a.y, Aa.y);  FMA2SH(aB3, E1b.y, Ab.y);
        e1A = E1a.y; Y0A = Y1a;
        e1B = E1b.y; Y0B = Y1b;
    }
    {
        const float a32 = xs[k0a + 32];
        const float a33 = xs[k0a + 33];
        unsigned int acc[4] = {aA0, aA1, aA2, aA3};
        #pragma unroll
        for (int s = 0; s < 4; s++) {
            float W33 = xs[BA + 33 + s];
            float W34 = xs[BA + 34 + s];
            float d32 = a32 - W33;
            float d33 = a33 - W34;
            float u32 = fmaf(d32, d32, -Rs2);
            float u33 = fmaf(d33, d33, -Rs2);
            unsigned int ext = (__float_as_uint(u32) & 0x80000000u)
                             | ((__float_as_uint(u33) >> 1) & 0x40000000u);
            int rem = remA - s;
            unsigned int mask = (rem >= 32) ? 0xffffffffu
                              : ((rem <= 0) ? 0u : (0xffffffffu << (32 - rem)));
            unsigned int S1 = __funnelshift_l(ext, acc[s], 1);
            unsigned int S2 = __funnelshift_l(ext, acc[s], 2);
            unsigned int mm = acc[s] & S1 & mask;
            cm  += __popc(mm);
            cm1 += __popc(mm & S2);
        }
    }
    {
        const float a32 = xs[k0b + 32];
        const float a33 = xs[k0b + 33];
        unsigned int acc[4] = {aB0, aB1, aB2, aB3};
        #pragma unroll
        for (int s = 0; s < 4; s++) {
            float W33 = xs[BB + 33 + s];
            float W34 = xs[BB + 34 + s];
            float d32 = a32 - W33;
            float d33 = a33 - W34;
            float u32 = fmaf(d32, d32, -Rs2);
            float u33 = fmaf(d33, d33, -Rs2);
            unsigned int ext = (__float_as_uint(u32) & 0x80000000u)
                             | ((__float_as_uint(u33) >> 1) & 0x40000000u);
            int rem = remB - s;
            unsigned int mask = (rem >= 32) ? 0xffffffffu
                              : ((rem <= 0) ? 0u : (0xffffffffu << (32 - rem)));
            unsigned int S1 = __funnelshift_l(ext, acc[s], 1);
            unsigned int S2 = __funnelshift_l(ext, acc[s], 2);
            unsigned int mm = acc[s] & S1 & mask;
            cm  += __popc(mm);
            cm1 += __popc(mm & S2);
        }
    }
}

__global__ __launch_bounds__(NTHR, 1)
void sampen_kernel(const float* __restrict__ pred, const float* __restrict__ tgt,
                   float* __restrict__ out) {
    __shared__ __align__(16) float xs[PAD];
    __shared__ __align__(16) float ys[PAD];     // ys[i] = xs[i+1]
    __shared__ double redA[NWARP], redB[NWARP];
    __shared__ unsigned int redc[NWARP], redc1[NWARP];
    __shared__ float s_thresh2;

    const int s   = blockIdx.x;
    const int tid = threadIdx.x;
    const float* src = (s < 64) ? (pred + (size_t)s * T_LEN)
                                : (tgt  + (size_t)(s - 64) * T_LEN);

    // ---- load raw signal + zero pad ----
    float v0 = src[tid];
    float v1 = src[tid + NTHR];
    xs[tid]        = v0;
    xs[tid + NTHR] = v1;
    for (int i = T_LEN + tid; i < PAD; i += NTHR) xs[i] = 0.0f;

    // ---- std (ddof=1) in double; mean cancels inside |xi-xj|:
    //      squared scaled threshold Rs2 = (R*(std+eps))^2 ----
    double ls  = (double)v0 + (double)v1;
    double ls2 = (double)v0 * (double)v0 + (double)v1 * (double)v1;
    #pragma unroll
    for (int o = 16; o > 0; o >>= 1) {
        ls  += __shfl_down_sync(0xffffffffu, ls,  o);
        ls2 += __shfl_down_sync(0xffffffffu, ls2, o);
    }
    if ((tid & 31) == 0) { redA[tid >> 5] = ls; redB[tid >> 5] = ls2; }
    __syncthreads();
    // build shifted copy (xs fully visible now); overlaps with tid0's reduction
    for (int i = tid; i < PAD - 1; i += NTHR) ys[i] = xs[i + 1];
    if (tid == 0) {
        ys[PAD - 1] = 0.0f;
        double S = 0.0, S2 = 0.0;
        #pragma unroll
        for (int w = 0; w < NWARP; w++) { S += redA[w]; S2 += redB[w]; }
        double var = (S2 - S * S / (double)T_LEN) / (double)(T_LEN - 1);
        double sd  = sqrt(var);
        double rs  = (double)RR * (sd + 1e-8);
        s_thresh2  = (float)(rs * rs);
    }
    __syncthreads();
    const float Rs2 = s_thresh2;
    const u64 NEG1 = 0xBF800000BF800000ull;               // (-1.0f, -1.0f)
    const unsigned int nr = __float_as_uint(-Rs2);
    const u64 NRS2 = (u64)nr | ((u64)nr << 32);           // (-Rs2, -Rs2)

    // ---- upper-triangle counting: 4-diagonal groups, 2-unit ILP, 4 slots ----
    // Pair (P, 255-P): exactly 33 units. Thread (P = tid&127, sg = tid>>7 in [0,4))
    // owns units [g0, g1): counts {8,8,8,9}; single-unit tail only for sg==3.
    const int P  = tid & 127;
    const int sg = tid >> 7;           // warp-uniform, 0..3
    const int dA = 4 * P + 1;
    const int LA = NN - dA;            // 1021 - 4P
    const int dB = 1021 - 4 * P;       // partner group 255-P
    const int LB = NN - dB;            // 4P + 1
    const int CA = (LA + 31) >> 5;
    const int g0 = (sg * 33) >> 2;
    const int g1 = ((sg + 1) * 33) >> 2;

    unsigned int cm = 0, cm1 = 0;
    int j = g0;
    for (; j + 1 < g1; j += 2) {
        bool inA0  = (j < CA);
        int dbase0 = inA0 ? dA : dB;
        int c0     = inA0 ? j  : j - CA;
        int Lb0    = inA0 ? LA : LB;
        int jb     = j + 1;
        bool inA1  = (jb < CA);
        int dbase1 = inA1 ? dA : dB;
        int c1     = inA1 ? jb : jb - CA;
        int Lb1    = inA1 ? LA : LB;
        unit2_count(xs, ys, c0 << 5, dbase0, Lb0 - (c0 << 5),
                            c1 << 5, dbase1, Lb1 - (c1 << 5),
                    Rs2, NEG1, NRS2, cm, cm1);
    }
    if (j < g1) {                       // only sg == 3 (warp-uniform)
        bool inA  = (j < CA);
        int dbase = inA ? dA : dB;
        int c     = inA ? j  : j - CA;
        int Lb    = inA ? LA : LB;
        unit_count(xs, ys, c << 5, dbase, Lb - (c << 5), Rs2, NEG1, NRS2, cm, cm1);
    }

    // ---- reduce counts ----
    #pragma unroll
    for (int o = 16; o > 0; o >>= 1) {
        cm  += __shfl_down_sync(0xffffffffu, cm,  o);
        cm1 += __shfl_down_sync(0xffffffffu, cm1, o);
    }
    if ((tid & 31) == 0) { redc[tid >> 5] = cm; redc1[tid >> 5] = cm1; }
    __syncthreads();

    if (tid == 0) {
        unsigned int tm = 0, tm1 = 0;
        #pragma unroll
        for (int w = 0; w < NWARP; w++) { tm += redc[w]; tm1 += redc1[w]; }
        // symmetric matrix + zero diagonal: matches = NN + 2*upper
        unsigned int matches_m  = (unsigned int)NN + 2u * tm;
        unsigned int matches_m1 = (unsigned int)NN + 2u * tm1;
        float ratio = (float)matches_m1 / (float)matches_m;   // matches_m >= NN > 0
        ratio = fmaxf(ratio, 1e-30f);
        g_ent[s] = -logf(ratio);

        // ---- fused finalize: last block computes the MSE ----
        __threadfence();
        unsigned int old = atomicAdd(&g_barrier, 1);
        if (old == 127u) {
            g_barrier = 0;            // reset for next graph replay
            __threadfence();          // make all g_ent writes visible
            float acc = 0.0f;
            #pragma unroll
            for (int i = 0; i < 64; i++) {
                float dp = __ldcg(&g_ent[i]);
                float dt = __ldcg(&g_ent[64 + i]);
                float dd = dp - dt;
                acc += dd * dd;
            }
            out[0] = acc * (1.0f / 64.0f);
        }
    }
}

extern "C" void kernel_launch(void* const* d_in, const int* in_sizes, int n_in,
                              void* d_out, int out_size) {
    const float* pred = (const float*)d_in[0];
    const float* tgt  = (const float*)d_in[1];
    float* out = (float*)d_out;
    sampen_kernel<<<128, NTHR>>>(pred, tgt, out);
}

// round 13
// speedup vs baseline: 1.1306x; 1.0171x over previous
#include <cuda_runtime.h>
#include <math.h>

#define T_LEN 1024
#define NN    1022            /* templates */
#define PAD   1104
#define RR    0.2f
#define NTHR  384
#define NWARP (NTHR / 32)

typedef unsigned long long u64;

__device__ float g_ent[128];
__device__ unsigned int g_barrier;

__device__ __forceinline__ u64 fma2(u64 a, u64 b, u64 c) {
    u64 r;
    asm("fma.rn.f32x2 %0, %1, %2, %3;" : "=l"(r) : "l"(a), "l"(b), "l"(c));
    return r;
}
__device__ __forceinline__ unsigned int lo32(u64 v) { return (unsigned int)v; }
__device__ __forceinline__ unsigned int hi32(u64 v) { return (unsigned int)(v >> 32); }

// Two pairs (lower k first): d2 = fma2(W,-1,A); u2 = fma2(d2,d2,-Rs2);
// insert both sign bits MSB-first.
#define FMA2SH(acc, W, A)                                            \
    do {                                                             \
        u64 _d = fma2((W), NEG1, (A));                               \
        u64 _u = fma2(_d, _d, NRS2);                                 \
        (acc) = __funnelshift_l(lo32(_u), (acc), 1);                 \
        (acc) = __funnelshift_l(hi32(_u), (acc), 1);                 \
    } while (0)

// ---- single self-contained unit: chunk k0..k0+31 of diagonals
// dbase..dbase+3 (dbase ≡ 1 mod 4). Aligned ulonglong2 loads:
// evens from xs, odds from ys (ys[i] = xs[i+1]). ----
__device__ __forceinline__ void unit_count(const float* __restrict__ xs,
                                           const float* __restrict__ ys,
                                           int k0, int dbase, int remBase,
                                           float Rs2, u64 NEG1, u64 NRS2,
                                           unsigned int& cm, unsigned int& cm1) {
    const int B = k0 + dbase - 1;                     // ≡ 0 mod 4
    const ulonglong2* __restrict__ Ap = reinterpret_cast<const ulonglong2*>(xs + k0);
    const ulonglong2* __restrict__ Ep = reinterpret_cast<const ulonglong2*>(xs + B);
    const ulonglong2* __restrict__ Yp = reinterpret_cast<const ulonglong2*>(ys + B);
    unsigned int acc0 = 0, acc1 = 0, acc2 = 0, acc3 = 0;
    u64 e1 = Ep[0].y;
    ulonglong2 Y0 = Yp[0];
    #pragma unroll
    for (int q = 0; q < 8; q++) {
        ulonglong2 A  = Ap[q];
        ulonglong2 E1 = Ep[q + 1];
        ulonglong2 Y1 = Yp[q + 1];
        FMA2SH(acc0, Y0.x, A.x);  FMA2SH(acc0, Y0.y, A.y);   // s=0
        FMA2SH(acc1, e1,   A.x);  FMA2SH(acc1, E1.x, A.y);   // s=1
        FMA2SH(acc2, Y0.y, A.x);  FMA2SH(acc2, Y1.x, A.y);   // s=2
        FMA2SH(acc3, E1.x, A.x);  FMA2SH(acc3, E1.y, A.y);   // s=3
        e1 = E1.y; Y0 = Y1;
    }
    const float a32 = xs[k0 + 32];
    const float a33 = xs[k0 + 33];
    unsigned int acc[4] = {acc0, acc1, acc2, acc3};
    #pragma unroll
    for (int s = 0; s < 4; s++) {
        float W33 = xs[B + 33 + s];
        float W34 = xs[B + 34 + s];
        float d32 = a32 - W33;
        float d33 = a33 - W34;
        float u32 = fmaf(d32, d32, -Rs2);
        float u33 = fmaf(d33, d33, -Rs2);
        unsigned int ext = (__float_as_uint(u32) & 0x80000000u)
                         | ((__float_as_uint(u33) >> 1) & 0x40000000u);
        int rem = remBase - s;
        unsigned int mask = (rem >= 32) ? 0xffffffffu
                          : ((rem <= 0) ? 0u : (0xffffffffu << (32 - rem)));
        unsigned int S1 = __funnelshift_l(ext, acc[s], 1);
        unsigned int S2 = __funnelshift_l(ext, acc[s], 2);
        unsigned int mm = acc[s] & S1 & mask;
        cm  += __popc(mm);
        cm1 += __popc(mm & S2);
    }
}

// ---- two interleaved independent units (ILP x2) ----
__device__ __forceinline__ void unit2_count(const float* __restrict__ xs,
                                            const float* __restrict__ ys,
                                            int k0a, int dba, int remA,
                                            int k0b, int dbb, int remB,
                                            float Rs2, u64 NEG1, u64 NRS2,
                                            unsigned int& cm, unsigned int& cm1) {
    const int BA = k0a + dba - 1;
    const int BB = k0b + dbb - 1;
    const ulonglong2* __restrict__ ApA = reinterpret_cast<const ulonglong2*>(xs + k0a);
    const ulonglong2* __restrict__ EpA = reinterpret_cast<const ulonglong2*>(xs + BA);
    const ulonglong2* __restrict__ YpA = reinterpret_cast<const ulonglong2*>(ys + BA);
    const ulonglong2* __restrict__ ApB = reinterpret_cast<const ulonglong2*>(xs + k0b);
    const ulonglong2* __restrict__ EpB = reinterpret_cast<const ulonglong2*>(xs + BB);
    const ulonglong2* __restrict__ YpB = reinterpret_cast<const ulonglong2*>(ys + BB);
    unsigned int aA0 = 0, aA1 = 0, aA2 = 0, aA3 = 0;
    unsigned int aB0 = 0, aB1 = 0, aB2 = 0, aB3 = 0;
    u64 e1A = EpA[0].y;
    u64 e1B = EpB[0].y;
    ulonglong2 Y0A = YpA[0];
    ulonglong2 Y0B = YpB[0];
    #pragma unroll
    for (int q = 0; q < 8; q++) {
        ulonglong2 Aa  = ApA[q];
        ulonglong2 E1a = EpA[q + 1];
        ulonglong2 Y1a = YpA[q + 1];
        ulonglong2 Ab  = ApB[q];
        ulonglong2 E1b = EpB[q + 1];
        ulonglong2 Y1b = YpB[q + 1];
        FMA2SH(aA0, Y0A.x, Aa.x);  FMA2SH(aB0, Y0B.x, Ab.x);
        FMA2SH(aA0, Y0A.y, Aa.y);  FMA2SH(aB0, Y0B.y, Ab.y);
        FMA2SH(aA1, e1A,   Aa.x);  FMA2SH(aB1, e1B,   Ab.x);
        FMA2SH(aA1, E1a.x, Aa.y);  FMA2SH(aB1, E1b.x, Ab.y);
        FMA2SH(aA2, Y0A.y, Aa.x);  FMA2SH(aB2, Y0B.y, Ab.x);
        FMA2SH(aA2, Y1a.x, Aa.y);  FMA2SH(aB2, Y1b.x, Ab.y);
        FMA2SH(aA3, E1a.x, Aa.x);  FMA2SH(aB3, E1b.x, Ab.x);
        FMA2SH(aA3, E1a.y, Aa.y);  FMA2SH(aB3, E1b.y, Ab.y);
        e1A = E1a.y; Y0A = Y1a;
        e1B = E1b.y; Y0B = Y1b;
    }
    {
        const float a32 = xs[k0a + 32];
        const float a33 = xs[k0a + 33];
        unsigned int acc[4] = {aA0, aA1, aA2, aA3};
        #pragma unroll
        for (int s = 0; s < 4; s++) {
            float W33 = xs[BA + 33 + s];
            float W34 = xs[BA + 34 + s];
            float d32 = a32 - W33;
            float d33 = a33 - W34;
            float u32 = fmaf(d32, d32, -Rs2);
            float u33 = fmaf(d33, d33, -Rs2);
            unsigned int ext = (__float_as_uint(u32) & 0x80000000u)
                             | ((__float_as_uint(u33) >> 1) & 0x40000000u);
            int rem = remA - s;
            unsigned int mask = (rem >= 32) ? 0xffffffffu
                              : ((rem <= 0) ? 0u : (0xffffffffu << (32 - rem)));
            unsigned int S1 = __funnelshift_l(ext, acc[s], 1);
            unsigned int S2 = __funnelshift_l(ext, acc[s], 2);
            unsigned int mm = acc[s] & S1 & mask;
            cm  += __popc(mm);
            cm1 += __popc(mm & S2);
        }
    }
    {
        const float a32 = xs[k0b + 32];
        const float a33 = xs[k0b + 33];
        unsigned int acc[4] = {aB0, aB1, aB2, aB3};
        #pragma unroll
        for (int s = 0; s < 4; s++) {
            float W33 = xs[BB + 33 + s];
            float W34 = xs[BB + 34 + s];
            float d32 = a32 - W33;
            float d33 = a33 - W34;
            float u32 = fmaf(d32, d32, -Rs2);
            float u33 = fmaf(d33, d33, -Rs2);
            unsigned int ext = (__float_as_uint(u32) & 0x80000000u)
                             | ((__float_as_uint(u33) >> 1) & 0x40000000u);
            int rem = remB - s;
            unsigned int mask = (rem >= 32) ? 0xffffffffu
                              : ((rem <= 0) ? 0u : (0xffffffffu << (32 - rem)));
            unsigned int S1 = __funnelshift_l(ext, acc[s], 1);
            unsigned int S2 = __funnelshift_l(ext, acc[s], 2);
            unsigned int mm = acc[s] & S1 & mask;
            cm  += __popc(mm);
            cm1 += __popc(mm & S2);
        }
    }
}

__global__ __launch_bounds__(NTHR, 1)
void sampen_kernel(const float* __restrict__ pred, const float* __restrict__ tgt,
                   float* __restrict__ out) {
    __shared__ __align__(16) float xs[PAD];
    __shared__ __align__(16) float ys[PAD];     // ys[i] = xs[i+1]
    __shared__ double redA[NWARP], redB[NWARP];
    __shared__ unsigned int redc[NWARP], redc1[NWARP];
    __shared__ float s_thresh2;

    const int s   = blockIdx.x;
    const int tid = threadIdx.x;
    const float* src = (s < 64) ? (pred + (size_t)s * T_LEN)
                                : (tgt  + (size_t)(s - 64) * T_LEN);

    // ---- load raw signal (3 strided loads for 384 threads) + zero pad ----
    float v0 = src[tid];
    float v1 = src[tid + NTHR];
    float v2 = (tid + 2 * NTHR < T_LEN) ? src[tid + 2 * NTHR] : 0.0f;
    xs[tid]            = v0;
    xs[tid + NTHR]     = v1;
    if (tid + 2 * NTHR < T_LEN) xs[tid + 2 * NTHR] = v2;
    for (int i = T_LEN + tid; i < PAD; i += NTHR) xs[i] = 0.0f;

    // ---- std (ddof=1) in double; mean cancels inside |xi-xj|:
    //      squared scaled threshold Rs2 = (R*(std+eps))^2 ----
    double ls  = (double)v0 + (double)v1 + (double)v2;
    double ls2 = (double)v0 * (double)v0 + (double)v1 * (double)v1
               + (double)v2 * (double)v2;
    #pragma unroll
    for (int o = 16; o > 0; o >>= 1) {
        ls  += __shfl_down_sync(0xffffffffu, ls,  o);
        ls2 += __shfl_down_sync(0xffffffffu, ls2, o);
    }
    if ((tid & 31) == 0) { redA[tid >> 5] = ls; redB[tid >> 5] = ls2; }
    __syncthreads();
    // build shifted copy (xs fully visible now); overlaps with tid0's reduction
    for (int i = tid; i < PAD - 1; i += NTHR) ys[i] = xs[i + 1];
    if (tid == 0) {
        ys[PAD - 1] = 0.0f;
        double S = 0.0, S2 = 0.0;
        #pragma unroll
        for (int w = 0; w < NWARP; w++) { S += redA[w]; S2 += redB[w]; }
        double var = (S2 - S * S / (double)T_LEN) / (double)(T_LEN - 1);
        double sd  = sqrt(var);
        double rs  = (double)RR * (sd + 1e-8);
        s_thresh2  = (float)(rs * rs);
    }
    __syncthreads();
    const float Rs2 = s_thresh2;
    const u64 NEG1 = 0xBF800000BF800000ull;               // (-1.0f, -1.0f)
    const unsigned int nr = __float_as_uint(-Rs2);
    const u64 NRS2 = (u64)nr | ((u64)nr << 32);           // (-Rs2, -Rs2)

    // ---- upper-triangle counting: 4-diagonal groups, 2-unit ILP, 3 slots ----
    // Pair (P, 255-P): exactly 33 units. Thread (P = tid&127, sg = tid>>7 in [0,3))
    // owns 11 units: 5 x unit2 + 1 x unit1, IDENTICAL trip counts for all warps.
    const int P  = tid & 127;
    const int sg = tid >> 7;           // warp-uniform, 0..2
    const int dA = 4 * P + 1;
    const int LA = NN - dA;            // 1021 - 4P
    const int dB = 1021 - 4 * P;       // partner group 255-P
    const int LB = NN - dB;            // 4P + 1
    const int CA = (LA + 31) >> 5;
    const int g0 = sg * 11;
    const int g1 = g0 + 11;

    unsigned int cm = 0, cm1 = 0;
    int j = g0;
    #pragma unroll 1
    for (; j + 1 < g1; j += 2) {
        bool inA0  = (j < CA);
        int dbase0 = inA0 ? dA : dB;
        int c0     = inA0 ? j  : j - CA;
        int Lb0    = inA0 ? LA : LB;
        int jb     = j + 1;
        bool inA1  = (jb < CA);
        int dbase1 = inA1 ? dA : dB;
        int c1     = inA1 ? jb : jb - CA;
        int Lb1    = inA1 ? LA : LB;
        unit2_count(xs, ys, c0 << 5, dbase0, Lb0 - (c0 << 5),
                            c1 << 5, dbase1, Lb1 - (c1 << 5),
                    Rs2, NEG1, NRS2, cm, cm1);
    }
    {   // 11th unit (all warps, uniform)
        bool inA  = (j < CA);
        int dbase = inA ? dA : dB;
        int c     = inA ? j  : j - CA;
        int Lb    = inA ? LA : LB;
        unit_count(xs, ys, c << 5, dbase, Lb - (c << 5), Rs2, NEG1, NRS2, cm, cm1);
    }

    // ---- reduce counts ----
    #pragma unroll
    for (int o = 16; o > 0; o >>= 1) {
        cm  += __shfl_down_sync(0xffffffffu, cm,  o);
        cm1 += __shfl_down_sync(0xffffffffu, cm1, o);
    }
    if ((tid & 31) == 0) { redc[tid >> 5] = cm; redc1[tid >> 5] = cm1; }
    __syncthreads();

    if (tid == 0) {
        unsigned int tm = 0, tm1 = 0;
        #pragma unroll
        for (int w = 0; w < NWARP; w++) { tm += redc[w]; tm1 += redc1[w]; }
        // symmetric matrix + zero diagonal: matches = NN + 2*upper
        unsigned int matches_m  = (unsigned int)NN + 2u * tm;
        unsigned int matches_m1 = (unsigned int)NN + 2u * tm1;
        float ratio = (float)matches_m1 / (float)matches_m;   // matches_m >= NN > 0
        ratio = fmaxf(ratio, 1e-30f);
        g_ent[s] = -logf(ratio);

        // ---- fused finalize: last block computes the MSE ----
        __threadfence();
        unsigned int old = atomicAdd(&g_barrier, 1);
        if (old == 127u) {
            g_barrier = 0;            // reset for next graph replay
            __threadfence();          // make all g_ent writes visible
            float acc = 0.0f;
            #pragma unroll
            for (int i = 0; i < 64; i++) {
                float dp = __ldcg(&g_ent[i]);
                float dt = __ldcg(&g_ent[64 + i]);
                float dd = dp - dt;
                acc += dd * dd;
            }
            out[0] = acc * (1.0f / 64.0f);
        }
    }
}

extern "C" void kernel_launch(void* const* d_in, const int* in_sizes, int n_in,
                              void* d_out, int out_size) {
    const float* pred = (const float*)d_in[0];
    const float* tgt  = (const float*)d_in[1];
    float* out = (float*)d_out;
    sampen_kernel<<<128, NTHR>>>(pred, tgt, out);
}